// round 17
// baseline (speedup 1.0000x reference)
#include <cuda_runtime.h>
#include <cuda_fp16.h>
#include <cstdint>

#define BB 8
#define CC 128
#define C8N 16
#define DDN 16
#define HHN 32
#define WWN 32
#define HWN 1024
#define SSN 16384   // D*H*W

// ---------------- scratch (device globals; no runtime allocation) ----------
__device__ float    g_k  [BB * C8N * SSN];    // (B, C8, D, HW) fp32
__device__ float    g_q  [BB * C8N * SSN];
__device__ __half   g_vh [BB * CC  * SSN];    // conv output, fp16 (b,c,d,hw)
__device__ float    g_Ap [BB * HWN * HWN];    // attention logits fp32
__device__ __half   g_Aph[BB * HWN * HWN];    // softmaxed probs fp16
__device__ float    g_Ad [BB * DDN * DDN];    // depth attention
__device__ uint32_t g_wh [64 * 27 * CC];      // w_v half2 ci-pairs: [cp][j][co]
__device__ uint32_t g_xh [BB * 64 * SSN];     // x half2 ci-pairs: [b][cp][d*hw]

// ---------------- streams/events (created at load, before harness snapshot) -
static cudaStream_t g_sB;
static cudaEvent_t  g_e1, g_e2;
namespace {
struct _InitOnce {
    _InitOnce() {
        cudaStreamCreateWithFlags(&g_sB, cudaStreamNonBlocking);
        cudaEventCreateWithFlags(&g_e1, cudaEventDisableTiming);
        cudaEventCreateWithFlags(&g_e2, cudaEventDisableTiming);
    }
};
_InitOnce _init_once;
}

// ---------------- helpers ----------------------------------------------------
__device__ __forceinline__ uint32_t pack2h(float a, float b) {
    __half2 h = __floats2half2_rn(a, b);
    return *reinterpret_cast<uint32_t*>(&h);
}

__device__ __forceinline__ void mma16h(float* c, const uint32_t* a,
                                       uint32_t b0, uint32_t b1) {
    asm volatile(
        "mma.sync.aligned.m16n8k16.row.col.f32.f16.f16.f32 "
        "{%0,%1,%2,%3}, {%4,%5,%6,%7}, {%8,%9}, {%0,%1,%2,%3};"
        : "+f"(c[0]), "+f"(c[1]), "+f"(c[2]), "+f"(c[3])
        : "r"(a[0]), "r"(a[1]), "r"(a[2]), "r"(a[3]), "r"(b0), "r"(b1));
}

__device__ __forceinline__ uint32_t s2u(const void* p) {
    return (uint32_t)__cvta_generic_to_shared(p);
}

#define CP16(dst, src) \
    asm volatile("cp.async.cg.shared.global [%0], [%1], 16;" \
                 :: "r"(dst), "l"(src) : "memory")
#define CP16Z(dst, src, sz) \
    asm volatile("cp.async.cg.shared.global [%0], [%1], 16, %2;" \
                 :: "r"(dst), "l"(src), "r"(sz) : "memory")
#define CPCOMMIT() asm volatile("cp.async.commit_group;" ::: "memory")
#define CPWAIT0()  asm volatile("cp.async.wait_group 0;" ::: "memory")
#define CPWAIT1()  asm volatile("cp.async.wait_group 1;" ::: "memory")

// conv smem ring: 2 x (ws 9*8*128 + xs 8*248) uint32 words (128-co block)
#define CONV_WS_WORDS (9 * 8 * 128)       // 9216
#define CONV_XS_CI    248                 // 6 rows * 40 words + 8 pad
#define CONV_XS_WORDS (8 * CONV_XS_CI)    // 1984
#define CONV_STAGE_WORDS (CONV_WS_WORDS + CONV_XS_WORDS)   // 11200
#define CONV_SMEM_BYTES (2 * CONV_STAGE_WORDS * 4)         // 89600
// patt smem ring: 3 x (Vs 128*20 + Ps 128*20) words (128m x 128j block)
// epilogue reuses ring: sV 128x68 words + sAd 16x17 floats
#define PATT_V_WORDS (128 * 20)
#define PATT_P_WORDS (128 * 20)
#define PATT_STAGE_WORDS (PATT_V_WORDS + PATT_P_WORDS)     // 5120
#define PATT_SMEM_BYTES (3 * PATT_STAGE_WORDS * 4)         // 61440

// ---------------- kernel 1: fused k/q 1x1x1 convs + x->fp16 ci-pairs --------
__global__ void __launch_bounds__(256) kqx_kernel(
    const float* __restrict__ x, const float* __restrict__ wk,
    const float* __restrict__ bk, const float* __restrict__ wq,
    const float* __restrict__ bq) {
    __shared__ float swk[C8N * CC];
    __shared__ float swq[C8N * CC];
    const int b   = blockIdx.y;
    const int tid = threadIdx.x;
    for (int i = tid; i < C8N * CC; i += 256) { swk[i] = wk[i]; swq[i] = wq[i]; }
    __syncthreads();

    const int p = blockIdx.x * 512 + tid * 2;
    const float* xp = x + (size_t)b * CC * SSN + p;
    uint32_t*   xhp = g_xh + (size_t)b * 64 * SSN + p;

    float akx[C8N], aky[C8N], aqx[C8N], aqy[C8N];
#pragma unroll
    for (int o = 0; o < C8N; o++) { akx[o]=aky[o]=aqx[o]=aqy[o]=0.f; }

    float2 xe = make_float2(0.f, 0.f);
    for (int c = 0; c < CC; c++) {
        float2 xv = *(const float2*)(xp + (size_t)c * SSN);
        if (c & 1) {
            uint2 w;
            w.x = pack2h(xe.x, xv.x);
            w.y = pack2h(xe.y, xv.y);
            *(uint2*)(xhp + (size_t)(c >> 1) * SSN) = w;
        } else {
            xe = xv;
        }
#pragma unroll
        for (int o = 0; o < C8N; o++) {
            float wkv = swk[o * CC + c];
            float wqv = swq[o * CC + c];
            akx[o] += wkv * xv.x;  aky[o] += wkv * xv.y;
            aqx[o] += wqv * xv.x;  aqy[o] += wqv * xv.y;
        }
    }
    float* ko = g_k + (size_t)b * C8N * SSN + p;
    float* qo = g_q + (size_t)b * C8N * SSN + p;
#pragma unroll
    for (int o = 0; o < C8N; o++) {
        float bkv = bk[o], bqv = bq[o];
        ko[o * SSN]     = akx[o] + bkv;
        ko[o * SSN + 1] = aky[o] + bkv;
        qo[o * SSN]     = aqx[o] + bqv;
        qo[o * SSN + 1] = aqy[o] + bqv;
    }
}

// ---------------- kernel 2a: transpose + fp16-pack conv weights -------------
__global__ void wtrans_kernel(const float* __restrict__ wv) {
    int idx = blockIdx.x * 256 + threadIdx.x;           // 64*27*128
    if (idx < 64 * 27 * CC) {
        int o  = idx & 127;
        int r  = idx >> 7;
        int cp = r / 27;
        int j  = r % 27;
        float lo = wv[(o * CC + 2 * cp)     * 27 + j];
        float hi = wv[(o * CC + 2 * cp + 1) * 27 + j];
        g_wh[(cp * 27 + j) * CC + o] = pack2h(lo, hi);
    }
}

// ---------------- kernel 2b: 3x3x3 conv, FP16 mma k16, 2-deep, 2 blocks/SM --
// block (h-quad, d, b): 128 co x 128 positions (4 h-rows x 32 w).
// 128 threads, 4 warps 2m x 2n, warp 64co x 64pos. stage = (kd, 16 ci).
__global__ void __launch_bounds__(128, 2) conv_mma_kernel(
    const float* __restrict__ bv) {
    extern __shared__ uint32_t smem[];
    const int b   = blockIdx.z;
    const int d   = blockIdx.y;
    const int h0  = blockIdx.x * 4;
    const int tid  = threadIdx.x;
    const int warp = tid >> 5, lane = tid & 31;
    const int mg = warp >> 1, ng = warp & 1;
    const int co_w = mg * 64, pos_w = ng * 64;
    const int row = lane >> 2, kcol = lane & 3;
    const int sw0 = 8 * kcol;

    int kdk[3], kdz[3], nkd = 0;
#pragma unroll
    for (int kd = 0; kd < 3; kd++) {
        int zd = d + kd - 1;
        if (zd >= 0 && zd < DDN) { kdk[nkd] = kd; kdz[nkd] = zd; nkd++; }
    }
    const int NS = nkd * 8;

    float acc[4][8][4];
#pragma unroll
    for (int mt = 0; mt < 4; mt++)
#pragma unroll
        for (int nt = 0; nt < 8; nt++)
#pragma unroll
            for (int i = 0; i < 4; i++) acc[mt][nt][i] = 0.f;

    auto issue = [&](int s, int st) {
        uint32_t* wsb = smem + st * CONV_STAGE_WORDS;
        uint32_t* xsb = wsb + CONV_WS_WORDS;
        int ikd = s >> 3, cp0 = (s & 7) * 8;
        int kd = kdk[ikd], zd = kdz[ikd];
        // weights: 9 j x 8 ci-pairs x 128 co words = 2304 16B copies
        for (int c = tid; c < 2304; c += 128) {
            int wo = c * 4;
            int j  = wo >> 10;              // /1024
            int r  = wo & 1023;
            int pi = r >> 7;
            int o  = r & 127;
            CP16(s2u(wsb + (j * 8 + pi) * 128 + (o ^ (8 * (pi & 3)))),
                 g_wh + ((cp0 + pi) * 27 + kd * 9 + j) * CC + o);
        }
        // x slab: 8 ci-pairs, rows h0-1..h0+4 (6 rows), w halo, half2 words
        for (int i = tid; i < 480; i += 128) {
            int pi  = i / 60;
            int rem = i % 60;
            int r   = rem / 10;
            int k   = rem % 10;
            int hh  = h0 - 1 + r;
            int w0  = k * 4 - 4;
            bool ok = (hh >= 0) && (hh < HHN) && (k >= 1) && (k <= 8);
            const uint32_t* src = g_xh +
                ((size_t)b * 64 + cp0 + pi) * SSN + zd * HWN + (ok ? hh * WWN + w0 : 0);
            CP16Z(s2u(xsb + pi * CONV_XS_CI + r * 40 + k * 4), src, ok ? 16u : 0u);
        }
    };

    issue(0, 0); CPCOMMIT();

    for (int s = 0; s < NS; s++) {
        if (s + 1 < NS) {
            issue(s + 1, (s + 1) & 1);
            CPCOMMIT();
            CPWAIT1();
        } else {
            CPWAIT0();
        }
        __syncthreads();

        const uint32_t* wsb = smem + (s & 1) * CONV_STAGE_WORDS;
        const uint32_t* xsb = wsb + CONV_WS_WORDS;
#pragma unroll
        for (int j = 0; j < 9; j++) {
            const int kh = j / 3, kw = j % 3;
            uint32_t a[4][4];
#pragma unroll
            for (int mt = 0; mt < 4; mt++) {
                int cb = co_w + mt * 16;
                a[mt][0] = wsb[(j * 8 + kcol)     * 128 + ((cb + row)     ^ sw0)];
                a[mt][1] = wsb[(j * 8 + kcol)     * 128 + ((cb + row + 8) ^ sw0)];
                a[mt][2] = wsb[(j * 8 + kcol + 4) * 128 + ((cb + row)     ^ sw0)];
                a[mt][3] = wsb[(j * 8 + kcol + 4) * 128 + ((cb + row + 8) ^ sw0)];
            }
#pragma unroll
            for (int nt = 0; nt < 8; nt++) {
                int n0 = pos_w + nt * 8;
                int ht = (n0 >> 5) + kh;
                int wq = (n0 & 31) + row + kw + 3;
                uint32_t b0 = xsb[kcol       * CONV_XS_CI + ht * 40 + wq];
                uint32_t b1 = xsb[(kcol + 4) * CONV_XS_CI + ht * 40 + wq];
                mma16h(acc[0][nt], a[0], b0, b1);
                mma16h(acc[1][nt], a[1], b0, b1);
                mma16h(acc[2][nt], a[2], b0, b1);
                mma16h(acc[3][nt], a[3], b0, b1);
            }
        }
        __syncthreads();   // compute done before next issue overwrites this buf
    }

    // epilogue: v = fp16(acc + bias), packed half2 along hw
    const int posbase = blockIdx.x * 128;
#pragma unroll
    for (int mt = 0; mt < 4; mt++) {
        int co = co_w + mt * 16 + row;
        float bv0 = bv[co], bv1 = bv[co + 8];
#pragma unroll
        for (int nt = 0; nt < 8; nt++) {
            int pos = posbase + pos_w + nt * 8 + kcol * 2;
            __half* p0 = g_vh + (((size_t)b * CC + co)     * DDN + d) * HWN + pos;
            __half* p1 = g_vh + (((size_t)b * CC + co + 8) * DDN + d) * HWN + pos;
            *(uint32_t*)p0 = pack2h(acc[mt][nt][0] + bv0, acc[mt][nt][1] + bv0);
            *(uint32_t*)p1 = pack2h(acc[mt][nt][2] + bv1, acc[mt][nt][3] + bv1);
        }
    }
}

// ---------------- kernel 3: cor[b,s,t] = sum_f K[b,f,s] Q[b,f,t] (fp32) -----
__global__ void __launch_bounds__(256) cor_kernel() {
    __shared__ float Ks[32][68];
    __shared__ float Qs[32][68];
    const int b  = blockIdx.z;
    const int s0 = blockIdx.y * 64;
    const int t0 = blockIdx.x * 64;
    const int tid = threadIdx.x;
    const int ty = tid >> 4, tx = tid & 15;
    const int lf = tid >> 4, l4 = (tid & 15) * 4;

    const float* Kb = g_k + (size_t)b * 256 * HWN;
    const float* Qb = g_q + (size_t)b * 256 * HWN;

    float acc[4][4];
#pragma unroll
    for (int i = 0; i < 4; i++)
#pragma unroll
        for (int j = 0; j < 4; j++) acc[i][j] = 0.f;

    for (int f0 = 0; f0 < 256; f0 += 32) {
#pragma unroll
        for (int half = 0; half < 2; half++) {
            float4 kv = *(const float4*)(Kb + (size_t)(f0 + half * 16 + lf) * HWN + s0 + l4);
            float4 qv = *(const float4*)(Qb + (size_t)(f0 + half * 16 + lf) * HWN + t0 + l4);
            int fr = half * 16 + lf;
            Ks[fr][l4] = kv.x; Ks[fr][l4+1] = kv.y; Ks[fr][l4+2] = kv.z; Ks[fr][l4+3] = kv.w;
            Qs[fr][l4] = qv.x; Qs[fr][l4+1] = qv.y; Qs[fr][l4+2] = qv.z; Qs[fr][l4+3] = qv.w;
        }
        __syncthreads();
#pragma unroll
        for (int ff = 0; ff < 32; ff++) {
            float rk[4], rq[4];
#pragma unroll
            for (int i = 0; i < 4; i++) rk[i] = Ks[ff][ty * 4 + i];
#pragma unroll
            for (int j = 0; j < 4; j++) rq[j] = Qs[ff][tx * 4 + j];
#pragma unroll
            for (int i = 0; i < 4; i++)
#pragma unroll
                for (int j = 0; j < 4; j++) acc[i][j] += rk[i] * rq[j];
        }
        __syncthreads();
    }
    float* Ab = g_Ap + (size_t)b * HWN * HWN;
#pragma unroll
    for (int i = 0; i < 4; i++) {
        float4 o4 = make_float4(acc[i][0], acc[i][1], acc[i][2], acc[i][3]);
        *(float4*)(Ab + (size_t)(s0 + ty * 4 + i) * HWN + t0 + tx * 4) = o4;
    }
}

// ---------------- kernel 4: row softmax fp32 -> fp16 probs ------------------
__global__ void __launch_bounds__(256) softmaxP_kernel() {
    __shared__ float sw1[8];
    __shared__ float sw2[8];
    const int row = blockIdx.x;
    const int tid = threadIdx.x;
    const int lane = tid & 31, wid = tid >> 5;
    const float4* p = (const float4*)(g_Ap + (size_t)row * HWN);
    float4 v = p[tid];
    float m = fmaxf(fmaxf(v.x, v.y), fmaxf(v.z, v.w));
#pragma unroll
    for (int o = 16; o > 0; o >>= 1)
        m = fmaxf(m, __shfl_xor_sync(0xffffffffu, m, o));
    if (lane == 0) sw1[wid] = m;
    __syncthreads();
    m = sw1[0];
#pragma unroll
    for (int i = 1; i < 8; i++) m = fmaxf(m, sw1[i]);

    v.x = __expf(v.x - m); v.y = __expf(v.y - m);
    v.z = __expf(v.z - m); v.w = __expf(v.w - m);
    float s = v.x + v.y + v.z + v.w;
#pragma unroll
    for (int o = 16; o > 0; o >>= 1)
        s += __shfl_xor_sync(0xffffffffu, s, o);
    if (lane == 0) sw2[wid] = s;
    __syncthreads();
    s = sw2[0];
#pragma unroll
    for (int i = 1; i < 8; i++) s += sw2[i];

    float inv = 1.f / s;
    uint2 o2;
    o2.x = pack2h(v.x * inv, v.y * inv);
    o2.y = pack2h(v.z * inv, v.w * inv);
    *(uint2*)(g_Aph + (size_t)row * HWN + tid * 4) = o2;
}

// ---------------- kernel 5: depth attention A_d (tiny) ----------------------
__global__ void __launch_bounds__(256) ad_kernel() {
    __shared__ float red[256];
    const int d = blockIdx.x;
    const int b = blockIdx.y;
    const int tid = threadIdx.x;
    const int e = tid & 15, part = tid >> 4;
    const float4* kp = (const float4*)(g_k + (((size_t)b * C8N + part) * DDN + d) * HWN);
    const float4* qp = (const float4*)(g_q + (((size_t)b * C8N + part) * DDN + e) * HWN);
    float s = 0.f;
    for (int i = 0; i < 256; i++) {
        float4 a = kp[i], c = qp[i];
        s += a.x * c.x + a.y * c.y + a.z * c.z + a.w * c.w;
    }
    red[tid] = s; __syncthreads();
    if (tid == 0) {
        float logit[16];
        for (int ee = 0; ee < 16; ee++) {
            float t = 0.f;
            for (int pp = 0; pp < 16; pp++) t += red[pp * 16 + ee];
            logit[ee] = t;
        }
        float mx = logit[0];
        for (int ee = 1; ee < 16; ee++) mx = fmaxf(mx, logit[ee]);
        float sum = 0.f;
        for (int ee = 0; ee < 16; ee++) { logit[ee] = __expf(logit[ee] - mx); sum += logit[ee]; }
        float inv = 1.f / sum;
        for (int ee = 0; ee < 16; ee++)
            g_Ad[((size_t)b * DDN + d) * DDN + ee] = logit[ee] * inv;
    }
}

// ---------------- kernel 7: out = gamma*(Patt + Datt) + x  (fused) ----------
// per b: M=2048, N=1024, K=1024. Block 128m x 128j, 8 warps 2m x 4n (64x32).
__global__ void __launch_bounds__(256, 2) patt_mma_kernel(
    const float* __restrict__ x, const float* __restrict__ gamma,
    float* __restrict__ out) {
    extern __shared__ uint32_t psm[];

    const int b  = blockIdx.z;
    const int m0 = blockIdx.y * 128;
    const int j0 = blockIdx.x * 128;
    const int tid  = threadIdx.x;
    const int warp = tid >> 5, lane = tid & 31;
    const int mg = warp >> 2, ng = warp & 3;
    const int m_w = mg * 64, j_w = ng * 32;
    const int row = lane >> 2, kcol = lane & 3;

    const __half* Vb = g_vh  + (size_t)b * 2048 * HWN;
    const __half* Pb = g_Aph + (size_t)b * HWN * HWN;

    float acc[4][4][4];
#pragma unroll
    for (int mt = 0; mt < 4; mt++)
#pragma unroll
        for (int nt = 0; nt < 4; nt++)
#pragma unroll
            for (int i = 0; i < 4; i++) acc[mt][nt][i] = 0.f;

    auto stage = [&](int t, int st) {
        uint32_t* Vsb = psm + st * PATT_STAGE_WORDS;
        uint32_t* Psb = Vsb + PATT_V_WORDS;
        int t0 = t * 32;                       // halfs
#pragma unroll
        for (int c = tid; c < 512; c += 256) {     // V: 128 rows x 4 16B-chunks
            int m = c >> 2, q = c & 3;
            CP16(s2u(Vsb + m * 20 + q * 4), Vb + (size_t)(m0 + m) * HWN + t0 + q * 8);
        }
#pragma unroll
        for (int c = tid; c < 512; c += 256) {     // P: 128 rows x 4 chunks
            int m = c >> 2, q = c & 3;
            CP16(s2u(Psb + m * 20 + q * 4), Pb + (size_t)(j0 + m) * HWN + t0 + q * 8);
        }
    };

    stage(0, 0); CPCOMMIT();
    stage(1, 1); CPCOMMIT();

    for (int t = 0; t < 32; t++) {
        CPWAIT1();
        __syncthreads();

        const int st = t % 3;
        const uint32_t* Vsb = psm + st * PATT_STAGE_WORDS;
        const uint32_t* Psb = Vsb + PATT_V_WORDS;
#pragma unroll
        for (int ks = 0; ks < 2; ks++) {
            int k0 = ks * 8;                   // word offset
            uint32_t a[4][4];
#pragma unroll
            for (int mt = 0; mt < 4; mt++) {
                int mb = m_w + mt * 16;
                a[mt][0] = Vsb[(mb + row)     * 20 + k0 + kcol];
                a[mt][1] = Vsb[(mb + row + 8) * 20 + k0 + kcol];
                a[mt][2] = Vsb[(mb + row)     * 20 + k0 + kcol + 4];
                a[mt][3] = Vsb[(mb + row + 8) * 20 + k0 + kcol + 4];
            }
#pragma unroll
            for (int nt = 0; nt < 4; nt++) {
                uint32_t b0 = Psb[(j_w + nt * 8 + row) * 20 + k0 + kcol];
                uint32_t b1 = Psb[(j_w + nt * 8 + row) * 20 + k0 + kcol + 4];
                mma16h(acc[0][nt], a[0], b0, b1);
                mma16h(acc[1][nt], a[1], b0, b1);
                mma16h(acc[2][nt], a[2], b0, b1);
                mma16h(acc[3][nt], a[3], b0, b1);
            }
        }
        if (t + 2 < 32) stage(t + 2, (t + 2) % 3);
        CPCOMMIT();
    }

    // ---- fused Datt + residual epilogue (reuse ring smem) ----
    CPWAIT0();
    __syncthreads();                       // all warps done with ring
    float* sAd = (float*)(psm + 128 * 68);
    {
        for (int c = tid; c < 2048; c += 256) {    // 128 rows x 16 16B-chunks
            int m = c >> 4, q = c & 15;
            CP16(s2u(psm + m * 68 + q * 4), Vb + (size_t)(m0 + m) * HWN + j0 + q * 8);
        }
        if (tid < 256) {
            int dD = tid >> 4, e = tid & 15;
            sAd[dD * 17 + e] = g_Ad[b * 256 + tid];
        }
        CPCOMMIT();
        CPWAIT0();
        __syncthreads();
    }

    const float g = gamma[0];
#pragma unroll
    for (int mt = 0; mt < 4; mt++) {
        const int mlb = m_w + mt * 16;
        const int m   = m0 + mlb + row;
#pragma unroll
        for (int nt = 0; nt < 4; nt++) {
            const int w  = (j_w >> 1) + nt * 4 + kcol;
            float2 d0 = make_float2(0.f, 0.f);
            float2 d1 = make_float2(0.f, 0.f);
#pragma unroll
            for (int dd = 0; dd < 16; dd++) {
                float2 v2 = __half22float2(*(const __half2*)(psm + (mlb + dd) * 68 + w));
                float a0 = sAd[row * 17 + dd];
                float a1 = sAd[(row + 8) * 17 + dd];
                d0.x += a0 * v2.x;  d0.y += a0 * v2.y;
                d1.x += a1 * v2.x;  d1.y += a1 * v2.y;
            }
            const int jj = j0 + j_w + nt * 8 + kcol * 2;
            size_t i0 = (size_t)b * 2048 * HWN + (size_t)m * HWN + jj;
            size_t i1 = i0 + (size_t)8 * HWN;
            float2 xv0 = *(const float2*)(x + i0);
            float2 xv1 = *(const float2*)(x + i1);
            float2 o0, o1;
            o0.x = g * (acc[mt][nt][0] + d0.x) + xv0.x;
            o0.y = g * (acc[mt][nt][1] + d0.y) + xv0.y;
            o1.x = g * (acc[mt][nt][2] + d1.x) + xv1.x;
            o1.y = g * (acc[mt][nt][3] + d1.y) + xv1.y;
            *(float2*)(out + i0) = o0;
            *(float2*)(out + i1) = o1;
        }
    }
}

// ---------------- launch ----------------------------------------------------
// Fork topology identical to R10/R15/R16 (proven graph-capturable).
extern "C" void kernel_launch(void* const* d_in, const int* in_sizes, int n_in,
                              void* d_out, int out_size) {
    const float* x     = (const float*)d_in[0];
    const float* gamma = (const float*)d_in[1];
    const float* w_k   = (const float*)d_in[2];
    const float* b_k   = (const float*)d_in[3];
    const float* w_q   = (const float*)d_in[4];
    const float* b_q   = (const float*)d_in[5];
    const float* w_v   = (const float*)d_in[6];
    const float* b_v   = (const float*)d_in[7];
    float* out = (float*)d_out;

    cudaFuncSetAttribute(conv_mma_kernel,
                         cudaFuncAttributeMaxDynamicSharedMemorySize, CONV_SMEM_BYTES);
    cudaFuncSetAttribute(patt_mma_kernel,
                         cudaFuncAttributeMaxDynamicSharedMemorySize, PATT_SMEM_BYTES);

    // main stream: kqx
    kqx_kernel<<<dim3(32, BB), 256>>>(x, w_k, b_k, w_q, b_q);
    cudaEventRecord(g_e1, 0);

    // side stream: cor -> softmax -> ad (needs only g_k/g_q); joins via g_e1
    cudaStreamWaitEvent(g_sB, g_e1, 0);
    cor_kernel<<<dim3(16, 16, BB), 256, 0, g_sB>>>();
    softmaxP_kernel<<<BB * HWN, 256, 0, g_sB>>>();
    ad_kernel<<<dim3(DDN, BB), 256, 0, g_sB>>>();
    cudaEventRecord(g_e2, g_sB);

    // main: wtrans + conv
    wtrans_kernel<<<(64 * 27 * CC + 255) / 256, 256>>>(w_v);
    conv_mma_kernel<<<dim3(8, DDN, BB), 128, CONV_SMEM_BYTES>>>(b_v);

    // join: fused patt needs conv (g_vh) + side chain (g_Aph, g_Ad)
    cudaStreamWaitEvent(0, g_e2, 0);
    patt_mma_kernel<<<dim3(8, 16, BB), 256, PATT_SMEM_BYTES>>>(x, gamma, out);
}